// round 8
// baseline (speedup 1.0000x reference)
#include <cuda_runtime.h>
#include <math_constants.h>

// Bidirectional Chamfer distance, B=4, N=M=4096, D=3, fp32.
// dist = |q|^2 + |t|^2 - 2 q.t
// Single launch: 1024 blocks (512 queries x 256-target tile), f32x2 FMA loop
// at the fp32-lane floor. Tail fused via tickets:
//   - per-(qblk,bz) group counter: 16th tile-block merges 16 tile partials
//     for its 512 queries, block-sums -> g_gsum[group]
//   - global counter: 64th group-last sums 64 group sums in fixed order,
//     writes out, resets counters (graph-replay safe). No spinning.

#define BATCH   4
#define NPTS    4096
#define THREADS 256
#define QPT     2
#define QBLK    (THREADS * QPT)      // 512 queries per block
#define NQBLK   (NPTS / QBLK)        // 8
#define NTTILE  16                   // target tiles
#define TT      (NPTS / NTTILE)      // 256 targets per tile
#define TTP     (TT / 2)             // 128 target pairs
#define NDIRB   (2 * BATCH)          // 8
#define NGROUP  (NQBLK * NDIRB)      // 64 groups of 16 tile-blocks
#define ENT     (NDIRB * NPTS)       // 32768 final entries

__device__ float        g_part[NTTILE * ENT];  // [tile][bz*NPTS+q]
__device__ float        g_gsum[NGROUP];
__device__ unsigned int g_gcount[NGROUP];      // zero-init; reset at end
__device__ unsigned int g_count;               // zero-init; reset at end

__global__ __launch_bounds__(THREADS)
void chamfer_kernel(const float* __restrict__ src,
                    const float* __restrict__ tgt,
                    float* __restrict__ out) {
    // s_xy[p] = (-2x0,-2x1,-2y0,-2y1), s_zw[p] = (-2z0,-2z1,|t0|^2,|t1|^2)
    __shared__ float4 s_xy[TTP];
    __shared__ float4 s_zw[TTP];
    __shared__ float  s_wsum[THREADS / 32];
    __shared__ bool   s_grouplast;

    const int tile = blockIdx.y;
    const int bz   = blockIdx.z;     // 0..7 = b*2 + dir
    const int b    = bz >> 1;
    const int dir  = bz & 1;

    const float* __restrict__ qbase = (dir ? tgt : src) + (size_t)b * NPTS * 3;
    const float* __restrict__ tbase = (dir ? src : tgt) + (size_t)b * NPTS * 3;

    // ---- preprocess this 256-target tile into paired f32x2 layout
    {
        const float4* __restrict__ t4 =
            reinterpret_cast<const float4*>(tbase + (size_t)tile * TT * 3);
        if (threadIdx.x < TT / 4) {
            int g = threadIdx.x;
            float4 A = t4[3 * g + 0];
            float4 Bv = t4[3 * g + 1];
            float4 C = t4[3 * g + 2];
            // pts: (A.x,A.y,A.z)(A.w,B.x,B.y)(B.z,B.w,C.x)(C.y,C.z,C.w)
            s_xy[2 * g + 0] = make_float4(-2.0f * A.x, -2.0f * A.w,
                                          -2.0f * A.y, -2.0f * Bv.x);
            s_zw[2 * g + 0] = make_float4(-2.0f * A.z, -2.0f * Bv.y,
                fmaf(A.x, A.x, fmaf(A.y, A.y, A.z * A.z)),
                fmaf(A.w, A.w, fmaf(Bv.x, Bv.x, Bv.y * Bv.y)));
            s_xy[2 * g + 1] = make_float4(-2.0f * Bv.z, -2.0f * C.y,
                                          -2.0f * Bv.w, -2.0f * C.z);
            s_zw[2 * g + 1] = make_float4(-2.0f * C.x, -2.0f * C.w,
                fmaf(Bv.z, Bv.z, fmaf(Bv.w, Bv.w, C.x * C.x)),
                fmaf(C.y, C.y, fmaf(C.z, C.z, C.w * C.w)));
        }
    }
    __syncthreads();

    // ---- 2 queries/thread, min over the tile
    const int q0 = blockIdx.x * QBLK + threadIdx.x;
    unsigned long long qx2[QPT], qy2[QPT], qz2[QPT];
    float q2[QPT], mn[QPT];
#pragma unroll
    for (int j = 0; j < QPT; j++) {
        int q = q0 + j * THREADS;
        float x = qbase[q * 3 + 0];
        float y = qbase[q * 3 + 1];
        float z = qbase[q * 3 + 2];
        asm("mov.b64 %0, {%1, %1};" : "=l"(qx2[j]) : "f"(x));
        asm("mov.b64 %0, {%1, %1};" : "=l"(qy2[j]) : "f"(y));
        asm("mov.b64 %0, {%1, %1};" : "=l"(qz2[j]) : "f"(z));
        q2[j] = fmaf(x, x, fmaf(y, y, z * z));
        mn[j] = CUDART_INF_F;
    }

    const ulonglong2* __restrict__ pXY = reinterpret_cast<const ulonglong2*>(s_xy);
    const ulonglong2* __restrict__ pZW = reinterpret_cast<const ulonglong2*>(s_zw);

    // per warp-iter: 2 LDS.128 (broadcast) + 6 FFMA2 (fma pipe) + 4 FMNMX (alu)
#pragma unroll 4
    for (int p = 0; p < TTP; p++) {
        ulonglong2 xy = pXY[p];   // (x0,x1),(y0,y1)
        ulonglong2 zw = pZW[p];   // (z0,z1),(w0,w1)
#pragma unroll
        for (int j = 0; j < QPT; j++) {
            float s0, s1;
            asm("{\n\t"
                ".reg .b64 d;\n\t"
                "fma.rn.f32x2 d, %2, %3, %4;\n\t"
                "fma.rn.f32x2 d, %5, %6, d;\n\t"
                "fma.rn.f32x2 d, %7, %8, d;\n\t"
                "mov.b64 {%0, %1}, d;\n\t"
                "}"
                : "=f"(s0), "=f"(s1)
                : "l"(zw.x), "l"(qz2[j]), "l"(zw.y),
                  "l"(xy.y), "l"(qy2[j]),
                  "l"(xy.x), "l"(qx2[j]));
            mn[j] = fminf(mn[j], fminf(s0, s1));
        }
    }

    // ---- store partial mins (|q|^2 folded in)
    {
        float* part = g_part + (size_t)tile * ENT + (size_t)bz * NPTS;
#pragma unroll
        for (int j = 0; j < QPT; j++)
            part[q0 + j * THREADS] = mn[j] + q2[j];
    }

    // ---- group ticket: 16th tile-block of (qblk, bz) merges
    const int group = bz * NQBLK + blockIdx.x;
    __threadfence();
    __syncthreads();
    if (threadIdx.x == 0) {
        unsigned int prev = atomicAdd(&g_gcount[group], 1u);
        s_grouplast = (prev == NTTILE - 1);
    }
    __syncthreads();
    if (!s_grouplast) return;
    __threadfence();  // acquire: make all 16 tiles' stores visible

    // merge 16 tiles for this group's 512 queries, then block-sum
    float local = 0.0f;
#pragma unroll
    for (int j = 0; j < QPT; j++) {
        int e = bz * NPTS + q0 + j * THREADS;
        float v = g_part[e];
#pragma unroll
        for (int t = 1; t < NTTILE; t++)
            v = fminf(v, g_part[(size_t)t * ENT + e]);
        local += v;
    }
#pragma unroll
    for (int off = 16; off > 0; off >>= 1)
        local += __shfl_down_sync(0xFFFFFFFFu, local, off);
    if ((threadIdx.x & 31) == 0) s_wsum[threadIdx.x >> 5] = local;
    __syncthreads();

    if (threadIdx.x == 0) {
        float gs = 0.0f;
#pragma unroll
        for (int w = 0; w < THREADS / 32; w++) gs += s_wsum[w];
        g_gsum[group] = gs;
        __threadfence();
        unsigned int prev = atomicAdd(&g_count, 1u);
        if (prev == NGROUP - 1) {   // final: fixed-order sum of 64 group sums
            __threadfence();
            float tot = 0.0f;
            for (int i = 0; i < NGROUP; i++) tot += g_gsum[i];
            out[0] = tot / (float)(BATCH * NPTS);
            // reset counters for next graph replay
            for (int i = 0; i < NGROUP; i++) g_gcount[i] = 0u;
            g_count = 0u;
        }
    }
}

extern "C" void kernel_launch(void* const* d_in, const int* in_sizes, int n_in,
                              void* d_out, int out_size) {
    const float* src = (const float*)d_in[0];  // (B, N, 3)
    const float* tgt = (const float*)d_in[1];  // (B, M, 3)
    float* out = (float*)d_out;

    dim3 grid(NQBLK, NTTILE, NDIRB);  // 8 x 16 x 8 = 1024 blocks
    chamfer_kernel<<<grid, THREADS>>>(src, tgt, out);
}

// round 11
// speedup vs baseline: 1.0325x; 1.0325x over previous
#include <cuda_runtime.h>
#include <math_constants.h>

// Bidirectional Chamfer distance, B=4, N=M=4096, D=3, fp32.
// dist = |q|^2 + |t|^2 - 2 q.t
// Single launch, 1024 blocks (512 queries x 256-target tile), f32x2 FMA loop
// at the fp32-lane floor. Tile results merged via atomicMax on monotone keys
// (key = ~f2key(d): decreasing in d, 0 == +inf sentinel -> zero-init works,
// group-last restores 0 for graph replay). Group ticket (16) -> group-last
// sums its 512 finals; global ticket (64) -> fixed-order final sum.

#define BATCH   4
#define NPTS    4096
#define THREADS 256
#define QPT     2
#define QBLK    (THREADS * QPT)      // 512 queries per block
#define NQBLK   (NPTS / QBLK)        // 8
#define NTTILE  16                   // target tiles
#define TT      (NPTS / NTTILE)      // 256 targets per tile
#define TTP     (TT / 2)             // 128 target pairs
#define NDIRB   (2 * BATCH)          // 8
#define NGROUP  (NQBLK * NDIRB)      // 64 groups of 16 tile-blocks
#define ENT     (NDIRB * NPTS)       // 32768 final entries

__device__ unsigned int g_key[ENT];       // zero-init == +inf; restored at end
__device__ float        g_gsum[NGROUP];
__device__ unsigned int g_gcount[NGROUP]; // zero-init; reset by group-last
__device__ unsigned int g_count;          // zero-init; reset by final block

// key(d) = ~f2key(d): monotone DECREASING in d; all finite d -> key > 0.
__device__ __forceinline__ unsigned int dkey(float f) {
    unsigned int u = __float_as_uint(f);
    unsigned int k = (u & 0x80000000u) ? ~u : (u | 0x80000000u);  // f2key
    return ~k;
}
__device__ __forceinline__ float key2f(unsigned int kk) {
    unsigned int k = ~kk;
    unsigned int u = (k & 0x80000000u) ? (k & 0x7FFFFFFFu) : ~k;
    return __uint_as_float(u);
}

__global__ __launch_bounds__(THREADS)
void chamfer_kernel(const float* __restrict__ src,
                    const float* __restrict__ tgt,
                    float* __restrict__ out) {
    // s_xy[p] = (-2x0,-2x1,-2y0,-2y1), s_zw[p] = (-2z0,-2z1,|t0|^2,|t1|^2)
    __shared__ float4 s_xy[TTP];
    __shared__ float4 s_zw[TTP];
    __shared__ float  s_wsum[THREADS / 32];
    __shared__ bool   s_grouplast;

    const int tile = blockIdx.y;
    const int bz   = blockIdx.z;     // 0..7 = b*2 + dir
    const int b    = bz >> 1;
    const int dir  = bz & 1;

    const float* __restrict__ qbase = (dir ? tgt : src) + (size_t)b * NPTS * 3;
    const float* __restrict__ tbase = (dir ? src : tgt) + (size_t)b * NPTS * 3;

    // ---- preprocess this 256-target tile into paired f32x2 layout
    {
        const float4* __restrict__ t4 =
            reinterpret_cast<const float4*>(tbase + (size_t)tile * TT * 3);
        if (threadIdx.x < TT / 4) {
            int g = threadIdx.x;
            float4 A = t4[3 * g + 0];
            float4 Bv = t4[3 * g + 1];
            float4 C = t4[3 * g + 2];
            // pts: (A.x,A.y,A.z)(A.w,B.x,B.y)(B.z,B.w,C.x)(C.y,C.z,C.w)
            s_xy[2 * g + 0] = make_float4(-2.0f * A.x, -2.0f * A.w,
                                          -2.0f * A.y, -2.0f * Bv.x);
            s_zw[2 * g + 0] = make_float4(-2.0f * A.z, -2.0f * Bv.y,
                fmaf(A.x, A.x, fmaf(A.y, A.y, A.z * A.z)),
                fmaf(A.w, A.w, fmaf(Bv.x, Bv.x, Bv.y * Bv.y)));
            s_xy[2 * g + 1] = make_float4(-2.0f * Bv.z, -2.0f * C.y,
                                          -2.0f * Bv.w, -2.0f * C.z);
            s_zw[2 * g + 1] = make_float4(-2.0f * C.x, -2.0f * C.w,
                fmaf(Bv.z, Bv.z, fmaf(Bv.w, Bv.w, C.x * C.x)),
                fmaf(C.y, C.y, fmaf(C.z, C.z, C.w * C.w)));
        }
    }
    __syncthreads();

    // ---- 2 queries/thread, min over the tile
    const int q0 = blockIdx.x * QBLK + threadIdx.x;
    unsigned long long qx2[QPT], qy2[QPT], qz2[QPT];
    float q2[QPT], mn[QPT];
#pragma unroll
    for (int j = 0; j < QPT; j++) {
        int q = q0 + j * THREADS;
        float x = qbase[q * 3 + 0];
        float y = qbase[q * 3 + 1];
        float z = qbase[q * 3 + 2];
        asm("mov.b64 %0, {%1, %1};" : "=l"(qx2[j]) : "f"(x));
        asm("mov.b64 %0, {%1, %1};" : "=l"(qy2[j]) : "f"(y));
        asm("mov.b64 %0, {%1, %1};" : "=l"(qz2[j]) : "f"(z));
        q2[j] = fmaf(x, x, fmaf(y, y, z * z));
        mn[j] = CUDART_INF_F;
    }

    const ulonglong2* __restrict__ pXY = reinterpret_cast<const ulonglong2*>(s_xy);
    const ulonglong2* __restrict__ pZW = reinterpret_cast<const ulonglong2*>(s_zw);

    // per warp-iter: 2 LDS.128 (broadcast) + 6 FFMA2 (fma pipe) + 4 FMNMX (alu)
#pragma unroll 4
    for (int p = 0; p < TTP; p++) {
        ulonglong2 xy = pXY[p];   // (x0,x1),(y0,y1)
        ulonglong2 zw = pZW[p];   // (z0,z1),(w0,w1)
#pragma unroll
        for (int j = 0; j < QPT; j++) {
            float s0, s1;
            asm("{\n\t"
                ".reg .b64 d;\n\t"
                "fma.rn.f32x2 d, %2, %3, %4;\n\t"
                "fma.rn.f32x2 d, %5, %6, d;\n\t"
                "fma.rn.f32x2 d, %7, %8, d;\n\t"
                "mov.b64 {%0, %1}, d;\n\t"
                "}"
                : "=f"(s0), "=f"(s1)
                : "l"(zw.x), "l"(qz2[j]), "l"(zw.y),
                  "l"(xy.y), "l"(qy2[j]),
                  "l"(xy.x), "l"(qx2[j]));
            mn[j] = fminf(mn[j], fminf(s0, s1));
        }
    }

    // ---- fold tile mins into the global key buffer (atomicMax, key dec. in d)
    const int e0 = bz * NPTS + q0;
#pragma unroll
    for (int j = 0; j < QPT; j++)
        atomicMax(&g_key[e0 + j * THREADS], dkey(mn[j] + q2[j]));

    // ---- group ticket: 16th tile-block of (qblk, bz) finalizes the group
    const int group = bz * NQBLK + blockIdx.x;
    __threadfence();
    __syncthreads();
    if (threadIdx.x == 0) {
        unsigned int prev = atomicAdd(&g_gcount[group], 1u);
        s_grouplast = (prev == NTTILE - 1);
    }
    __syncthreads();
    if (!s_grouplast) return;
    __threadfence();  // acquire: all 16 tiles' atomics visible

    // read this group's 512 final keys (contiguous), decode, restore sentinel
    float local = 0.0f;
#pragma unroll
    for (int j = 0; j < QPT; j++) {
        int e = e0 + j * THREADS;
        local += key2f(g_key[e]);
        g_key[e] = 0u;              // restore +inf sentinel for next replay
    }
#pragma unroll
    for (int off = 16; off > 0; off >>= 1)
        local += __shfl_down_sync(0xFFFFFFFFu, local, off);
    if ((threadIdx.x & 31) == 0) s_wsum[threadIdx.x >> 5] = local;
    __syncthreads();

    if (threadIdx.x == 0) {
        float gs = 0.0f;
#pragma unroll
        for (int w = 0; w < THREADS / 32; w++) gs += s_wsum[w];
        g_gsum[group] = gs;
        g_gcount[group] = 0u;       // reset group counter for next replay
        __threadfence();
        unsigned int prev = atomicAdd(&g_count, 1u);
        if (prev == NGROUP - 1) {   // final: fixed-order sum of 64 group sums
            __threadfence();
            float tot = 0.0f;
            for (int i = 0; i < NGROUP; i++) tot += g_gsum[i];
            out[0] = tot / (float)(BATCH * NPTS);
            g_count = 0u;           // reset for next graph replay
        }
    }
}

extern "C" void kernel_launch(void* const* d_in, const int* in_sizes, int n_in,
                              void* d_out, int out_size) {
    const float* src = (const float*)d_in[0];  // (B, N, 3)
    const float* tgt = (const float*)d_in[1];  // (B, M, 3)
    float* out = (float*)d_out;

    dim3 grid(NQBLK, NTTILE, NDIRB);  // 8 x 16 x 8 = 1024 blocks
    chamfer_kernel<<<grid, THREADS>>>(src, tgt, out);
}

// round 12
// speedup vs baseline: 1.1750x; 1.1379x over previous
#include <cuda_runtime.h>
#include <math_constants.h>

// Bidirectional Chamfer distance, B=4, N=M=4096, D=3, fp32.
// dist[b,n,m] = |q_n|^2 + |t_m|^2 - 2 q_n.t_m  -- computed ONCE per (n,m),
// serving BOTH directions: row-mins (s2t) in registers, col-mins (t2s) via
// per-lane tree + smem candidate buffer (no shuffles). 1.5x less FMA work
// than computing each direction separately.
// K1: 1024 blocks = (4 qblk x 64 ttile x 4 batch); block = 1024 queries
//     (8/thread, f32x2-packed pairs) x 64 broadcast targets.
//     Margins merged via atomicMax on monotone keys (0-sentinel == +inf).
// K2: 32768 keys -> fixed-order sum, last-block finalize, keys reset to 0.

#define BATCH   4
#define NPTS    4096
#define THREADS 128
#define QPT     8
#define QBLK    (THREADS * QPT)          // 1024 queries per block
#define NQBLK   (NPTS / QBLK)            // 4
#define TT      64                        // targets per block
#define NTTILE  (NPTS / TT)              // 64
#define NKEY    (2 * BATCH * NPTS)       // 32768: [0,16384) rows, rest cols
#define COLBASE (BATCH * NPTS)           // 16384
#define CSTRIDE 129                      // cand row stride (conflict-free)

#define R_THREADS 512
#define R_NBLK    (NKEY / R_THREADS)     // 64

__device__ unsigned int g_key[NKEY];     // zero-init == +inf; K2 restores 0
__device__ float        g_bsum[R_NBLK];
__device__ unsigned int g_count;         // zero-init; reset by final block

// key(d) = ~f2key(d): monotone DECREASING in d; all finite d -> key > 0.
__device__ __forceinline__ unsigned int dkey(float f) {
    unsigned int u = __float_as_uint(f);
    unsigned int k = (u & 0x80000000u) ? ~u : (u | 0x80000000u);
    return ~k;
}
__device__ __forceinline__ float key2f(unsigned int kk) {
    unsigned int k = ~kk;
    unsigned int u = (k & 0x80000000u) ? (k & 0x7FFFFFFFu) : ~k;
    return __uint_as_float(u);
}

__global__ __launch_bounds__(THREADS)
void chamfer_k1(const float* __restrict__ src,
                const float* __restrict__ tgt) {
    // sXY[t] = ((-2x,-2x),(-2y,-2y)), sZW[t] = ((-2z,-2z),(w,w)), w=|t|^2
    __shared__ ulonglong2 sXY[TT];
    __shared__ ulonglong2 sZW[TT];
    __shared__ float      s_cand[TT * CSTRIDE];  // [t][thread], stride 129

    const int qblk = blockIdx.x;
    const int tt   = blockIdx.y;
    const int b    = blockIdx.z;
    const int tid  = threadIdx.x;

    const float* __restrict__ qb = src + (size_t)b * NPTS * 3;  // rows: source
    const float* __restrict__ tb = tgt + (size_t)b * NPTS * 3;  // cols: target

    // ---- load + duplicate-pack this block's 64 targets
    if (tid < TT) {
        int m = tt * TT + tid;
        float x = tb[m * 3 + 0], y = tb[m * 3 + 1], z = tb[m * 3 + 2];
        float w = fmaf(x, x, fmaf(y, y, z * z));
        float nx = -2.0f * x, ny = -2.0f * y, nz = -2.0f * z;
        unsigned long long px, py, pz, pw;
        asm("mov.b64 %0, {%1, %1};" : "=l"(px) : "f"(nx));
        asm("mov.b64 %0, {%1, %1};" : "=l"(py) : "f"(ny));
        asm("mov.b64 %0, {%1, %1};" : "=l"(pz) : "f"(nz));
        asm("mov.b64 %0, {%1, %1};" : "=l"(pw) : "f"(w));
        sXY[tid] = make_ulonglong2(px, py);
        sZW[tid] = make_ulonglong2(pz, pw);
    }

    // ---- load 8 queries/thread as 4 f32x2 pairs; |q|^2 packed as chain base
    const int q0 = qblk * QBLK + tid;
    unsigned long long qx2[4], qy2[4], qz2[4], q22[4];
    float rm[QPT];
#pragma unroll
    for (int r = 0; r < 4; r++) {
        int qa = q0 + (2 * r) * THREADS;
        int qc = qa + THREADS;
        float xa = qb[qa * 3 + 0], ya = qb[qa * 3 + 1], za = qb[qa * 3 + 2];
        float xc = qb[qc * 3 + 0], yc = qb[qc * 3 + 1], zc = qb[qc * 3 + 2];
        asm("mov.b64 %0, {%1, %2};" : "=l"(qx2[r]) : "f"(xa), "f"(xc));
        asm("mov.b64 %0, {%1, %2};" : "=l"(qy2[r]) : "f"(ya), "f"(yc));
        asm("mov.b64 %0, {%1, %2};" : "=l"(qz2[r]) : "f"(za), "f"(zc));
        float q2a = fmaf(xa, xa, fmaf(ya, ya, za * za));
        float q2c = fmaf(xc, xc, fmaf(yc, yc, zc * zc));
        asm("mov.b64 %0, {%1, %2};" : "=l"(q22[r]) : "f"(q2a), "f"(q2c));
        rm[2 * r] = CUDART_INF_F;
        rm[2 * r + 1] = CUDART_INF_F;
    }
    __syncthreads();

    // ---- main loop: per step (1 broadcast target x 8 queries):
    //      8 packed fma-ops + 15 FMNMX (alu) + 1 STS + 2 LDS
#pragma unroll 4
    for (int t = 0; t < TT; t++) {
        ulonglong2 xy = sXY[t];   // .x=(-2x,-2x), .y=(-2y,-2y)
        ulonglong2 zw = sZW[t];   // .x=(-2z,-2z), .y=(w,w)
        float c[4];
#pragma unroll
        for (int r = 0; r < 4; r++) {
            float d0, d1;
            asm("{\n\t"
                ".reg .b64 d;\n\t"
                "fma.rn.f32x2 d, %2, %3, %4;\n\t"   // -2z*qz + |q|^2
                "fma.rn.f32x2 d, %5, %6, d;\n\t"    // -2y*qy
                "fma.rn.f32x2 d, %7, %8, d;\n\t"    // -2x*qx
                "add.rn.f32x2 d, d, %9;\n\t"        // + |t|^2
                "mov.b64 {%0, %1}, d;\n\t"
                "}"
                : "=f"(d0), "=f"(d1)
                : "l"(zw.x), "l"(qz2[r]), "l"(q22[r]),
                  "l"(xy.y), "l"(qy2[r]),
                  "l"(xy.x), "l"(qx2[r]),
                  "l"(zw.y));
            rm[2 * r]     = fminf(rm[2 * r], d0);
            rm[2 * r + 1] = fminf(rm[2 * r + 1], d1);
            c[r] = fminf(d0, d1);
        }
        // col candidate for target t over this thread's 8 queries
        s_cand[t * CSTRIDE + tid] = fminf(fminf(c[0], c[1]), fminf(c[2], c[3]));
    }

    // ---- row-min merges (d already contains |q|^2 and |t|^2)
#pragma unroll
    for (int j = 0; j < QPT; j++)
        atomicMax(&g_key[b * NPTS + q0 + j * THREADS], dkey(rm[j]));

    __syncthreads();

    // ---- col-min: threads 0..63 reduce 128 candidates for their target
    if (tid < TT) {
        const float* cr = s_cand + tid * CSTRIDE;
        float v0 = cr[0], v1 = cr[1], v2 = cr[2], v3 = cr[3];
#pragma unroll
        for (int i = 4; i < THREADS; i += 4) {
            v0 = fminf(v0, cr[i + 0]);
            v1 = fminf(v1, cr[i + 1]);
            v2 = fminf(v2, cr[i + 2]);
            v3 = fminf(v3, cr[i + 3]);
        }
        float v = fminf(fminf(v0, v1), fminf(v2, v3));
        atomicMax(&g_key[COLBASE + b * NPTS + tt * TT + tid], dkey(v));
    }
}

// K2: decode + sum all 32768 final keys; reset keys; last block finalizes.
__global__ __launch_bounds__(R_THREADS)
void chamfer_k2(float* __restrict__ out) {
    __shared__ float s_wsum[R_THREADS / 32];

    const int e = blockIdx.x * R_THREADS + threadIdx.x;
    float v = key2f(g_key[e]);
    g_key[e] = 0u;                      // restore +inf sentinel for replay

#pragma unroll
    for (int off = 16; off > 0; off >>= 1)
        v += __shfl_down_sync(0xFFFFFFFFu, v, off);
    if ((threadIdx.x & 31) == 0) s_wsum[threadIdx.x >> 5] = v;
    __syncthreads();

    if (threadIdx.x == 0) {
        float bs = 0.0f;
#pragma unroll
        for (int w = 0; w < R_THREADS / 32; w++) bs += s_wsum[w];
        g_bsum[blockIdx.x] = bs;
        __threadfence();
        unsigned int prev = atomicAdd(&g_count, 1u);
        if (prev == R_NBLK - 1) {       // last block: fixed-order final sum
            __threadfence();
            float tot = 0.0f;
            for (int i = 0; i < R_NBLK; i++) tot += g_bsum[i];
            out[0] = tot / (float)(BATCH * NPTS);
            g_count = 0u;               // reset for next graph replay
        }
    }
}

extern "C" void kernel_launch(void* const* d_in, const int* in_sizes, int n_in,
                              void* d_out, int out_size) {
    const float* src = (const float*)d_in[0];  // (B, N, 3)
    const float* tgt = (const float*)d_in[1];  // (B, M, 3)
    float* out = (float*)d_out;

    dim3 grid(NQBLK, NTTILE, BATCH);  // 4 x 64 x 4 = 1024 blocks
    chamfer_k1<<<grid, THREADS>>>(src, tgt);

    chamfer_k2<<<R_NBLK, R_THREADS>>>(out);
}